// round 1
// baseline (speedup 1.0000x reference)
#include <cuda_runtime.h>
#include <cstdint>

#define TOTAL   9216
#define DIM     2048
#define HEADS   16
#define HD      128
#define FDIM    8192
#define QKV3    6144

// ---------------- scratch (device globals: allocation-free) ----------------
__device__ float g_ln  [(size_t)TOTAL * DIM];
__device__ float g_qkv [(size_t)TOTAL * QKV3];
__device__ float g_attn[(size_t)TOTAL * DIM];
__device__ float g_h2  [(size_t)TOTAL * DIM];
__device__ float g_gate[(size_t)TOTAL * FDIM];
__device__ float g_up  [(size_t)TOTAL * FDIM];

__device__ const int c_seqlen[8] = {512, 1024, 2048, 768, 1536, 896, 1280, 1152};

// ---------------- helpers ----------------
__device__ __forceinline__ uint32_t f2tf32(float x) {
    uint32_t r;
    asm("cvt.rna.tf32.f32 %0, %1;" : "=r"(r) : "f"(x));
    return r;
}

__device__ __forceinline__ void mma_tf32(float* c, const uint32_t* a, const uint32_t* b) {
    asm("mma.sync.aligned.m16n8k8.row.col.f32.tf32.tf32.f32 "
        "{%0,%1,%2,%3},{%4,%5,%6,%7},{%8,%9},{%0,%1,%2,%3};"
        : "+f"(c[0]), "+f"(c[1]), "+f"(c[2]), "+f"(c[3])
        : "r"(a[0]), "r"(a[1]), "r"(a[2]), "r"(a[3]), "r"(b[0]), "r"(b[1]));
}

// ---------------- RMSNorm: one block per row of 2048 ----------------
__global__ __launch_bounds__(256) void rmsnorm_kernel(const float* __restrict__ x,
                                                      const float* __restrict__ w,
                                                      float* __restrict__ y)
{
    int row = blockIdx.x;
    const float4* xr = reinterpret_cast<const float4*>(x + (size_t)row * DIM);
    float4*       yr = reinterpret_cast<float4*>(y + (size_t)row * DIM);
    const float4* wr = reinterpret_cast<const float4*>(w);
    int tid = threadIdx.x;

    float4 v0 = xr[tid];
    float4 v1 = xr[tid + 256];
    float ss = v0.x*v0.x + v0.y*v0.y + v0.z*v0.z + v0.w*v0.w
             + v1.x*v1.x + v1.y*v1.y + v1.z*v1.z + v1.w*v1.w;
    #pragma unroll
    for (int o = 16; o; o >>= 1) ss += __shfl_xor_sync(0xffffffffu, ss, o);

    __shared__ float red[8];
    __shared__ float stot;
    if ((tid & 31) == 0) red[tid >> 5] = ss;
    __syncthreads();
    if (tid == 0) {
        float t = 0.f;
        #pragma unroll
        for (int i = 0; i < 8; i++) t += red[i];
        stot = rsqrtf(t * (1.0f / (float)DIM) + 1e-6f);
    }
    __syncthreads();
    float r = stot;

    float4 w0 = wr[tid], w1 = wr[tid + 256];
    float4 o0 = make_float4(v0.x*r*w0.x, v0.y*r*w0.y, v0.z*r*w0.z, v0.w*r*w0.w);
    float4 o1 = make_float4(v1.x*r*w1.x, v1.y*r*w1.y, v1.z*r*w1.z, v1.w*r*w1.w);
    yr[tid] = o0;
    yr[tid + 256] = o1;
}

// ---------------- TF32 GEMM: C[M,N] = A[M,K] * B[N,K]^T (+bias)(+resid) ----------------
// 128x128x32 tile, 256 threads (8 warps as 2x4), warp tile 64x32.
// Smem m-major with pad 4 (stride 36): conflict-free fragment LDS.
#define GSTRIDE 36

__global__ __launch_bounds__(256) void gemm_tf32_kernel(
    const float* __restrict__ A, const float* __restrict__ B,
    const float* __restrict__ bias, const float* __restrict__ resid,
    float* __restrict__ C, int M, int N, int K)
{
    __shared__ uint32_t As[128 * GSTRIDE];
    __shared__ uint32_t Bs[128 * GSTRIDE];

    const int tid  = threadIdx.x;
    const int lane = tid & 31, warp = tid >> 5;
    const int lq = lane >> 2, lr = lane & 3;
    const int wm = (warp >> 2) * 64, wn = (warp & 3) * 32;
    const int bm = blockIdx.y * 128, bn = blockIdx.x * 128;

    float acc[4][4][4];
    #pragma unroll
    for (int mf = 0; mf < 4; mf++)
        #pragma unroll
        for (int nf = 0; nf < 4; nf++)
            #pragma unroll
            for (int e = 0; e < 4; e++) acc[mf][nf][e] = 0.f;

    const float* Abase = A + (size_t)bm * K;
    const float* Bbase = B + (size_t)bn * K;

    for (int k0 = 0; k0 < K; k0 += 32) {
        #pragma unroll
        for (int j = 0; j < 4; j++) {
            int i = tid + j * 256;
            int r = i >> 3, kg = (i & 7) << 2;
            float4 va = *reinterpret_cast<const float4*>(Abase + (size_t)r * K + k0 + kg);
            uint4 pa;
            pa.x = f2tf32(va.x); pa.y = f2tf32(va.y); pa.z = f2tf32(va.z); pa.w = f2tf32(va.w);
            *reinterpret_cast<uint4*>(&As[r * GSTRIDE + kg]) = pa;
            float4 vb = *reinterpret_cast<const float4*>(Bbase + (size_t)r * K + k0 + kg);
            uint4 pb;
            pb.x = f2tf32(vb.x); pb.y = f2tf32(vb.y); pb.z = f2tf32(vb.z); pb.w = f2tf32(vb.w);
            *reinterpret_cast<uint4*>(&Bs[r * GSTRIDE + kg]) = pb;
        }
        __syncthreads();

        #pragma unroll
        for (int ks = 0; ks < 4; ks++) {
            int kk = ks * 8;
            uint32_t af[4][4], bf[4][2];
            #pragma unroll
            for (int mf = 0; mf < 4; mf++) {
                int mrow = wm + mf * 16 + lq;
                af[mf][0] = As[mrow * GSTRIDE + kk + lr];
                af[mf][1] = As[(mrow + 8) * GSTRIDE + kk + lr];
                af[mf][2] = As[mrow * GSTRIDE + kk + lr + 4];
                af[mf][3] = As[(mrow + 8) * GSTRIDE + kk + lr + 4];
            }
            #pragma unroll
            for (int nf = 0; nf < 4; nf++) {
                int ncol = wn + nf * 8 + lq;
                bf[nf][0] = Bs[ncol * GSTRIDE + kk + lr];
                bf[nf][1] = Bs[ncol * GSTRIDE + kk + lr + 4];
            }
            #pragma unroll
            for (int mf = 0; mf < 4; mf++)
                #pragma unroll
                for (int nf = 0; nf < 4; nf++)
                    mma_tf32(acc[mf][nf], af[mf], bf[nf]);
        }
        __syncthreads();
    }

    // epilogue
    #pragma unroll
    for (int mf = 0; mf < 4; mf++) {
        #pragma unroll
        for (int nf = 0; nf < 4; nf++) {
            int r0 = bm + wm + mf * 16 + lq;
            int c0 = bn + wn + nf * 8 + lr * 2;
            float b0 = 0.f, b1 = 0.f;
            if (bias) { b0 = bias[c0]; b1 = bias[c0 + 1]; }
            float2 v0 = make_float2(acc[mf][nf][0] + b0, acc[mf][nf][1] + b1);
            float2 v1 = make_float2(acc[mf][nf][2] + b0, acc[mf][nf][3] + b1);
            if (resid) {
                float2 ra = *reinterpret_cast<const float2*>(resid + (size_t)r0 * N + c0);
                float2 rb = *reinterpret_cast<const float2*>(resid + (size_t)(r0 + 8) * N + c0);
                v0.x += ra.x; v0.y += ra.y;
                v1.x += rb.x; v1.y += rb.y;
            }
            *reinterpret_cast<float2*>(C + (size_t)r0 * N + c0) = v0;
            *reinterpret_cast<float2*>(C + (size_t)(r0 + 8) * N + c0) = v1;
        }
    }
}

// ---------------- Flash attention (tf32 mma, online softmax) ----------------
// grid (144 q-tiles, 16 heads), 128 threads (4 warps), 64-row Q tile, 64-row K/V tiles.
#define QK_STRIDE 132   // m-major [64][128] pad 4
#define V_STRIDE  136   // k-major [64][128] pad 8
#define P_STRIDE  68    // per-warp [16][64] pad 4
#define LOG2E 1.4426950408889634f

#define ATTN_SMEM_WORDS (64*QK_STRIDE*2 + 64*V_STRIDE + 4*16*P_STRIDE)

__global__ __launch_bounds__(128) void attn_kernel(const float* __restrict__ qkv,
                                                   float* __restrict__ out)
{
    extern __shared__ uint32_t sm[];
    uint32_t* Qs = sm;
    uint32_t* Ks = Qs + 64 * QK_STRIDE;
    uint32_t* Vs = Ks + 64 * QK_STRIDE;
    uint32_t* Ps = Vs + 64 * V_STRIDE;

    const int tile = blockIdx.x;
    const int h    = blockIdx.y;

    int seq_start = 0, q0 = 0;
    {
        int acc = 0, start = 0;
        #pragma unroll
        for (int s = 0; s < 8; s++) {
            int nt = c_seqlen[s] >> 6;
            if (tile >= acc && tile < acc + nt) { seq_start = start; q0 = (tile - acc) << 6; }
            acc += nt; start += c_seqlen[s];
        }
    }

    const int tid = threadIdx.x, lane = tid & 31, warp = tid >> 5;
    const int lq = lane >> 2, lr = lane & 3;

    // load Q tile (64 x 128), m-major
    {
        const size_t qbase = (size_t)(seq_start + q0) * QKV3 + h * HD;
        #pragma unroll
        for (int j = 0; j < 16; j++) {
            int i = tid + j * 128;
            int r = i >> 5, dg = (i & 31) << 2;
            float4 v = *reinterpret_cast<const float4*>(qkv + qbase + (size_t)r * QKV3 + dg);
            uint4 p;
            p.x = f2tf32(v.x); p.y = f2tf32(v.y); p.z = f2tf32(v.z); p.w = f2tf32(v.w);
            *reinterpret_cast<uint4*>(&Qs[r * QK_STRIDE + dg]) = p;
        }
    }

    float oacc[16][4];
    #pragma unroll
    for (int nf = 0; nf < 16; nf++)
        #pragma unroll
        for (int e = 0; e < 4; e++) oacc[nf][e] = 0.f;
    float m0 = -1e30f, m1 = -1e30f, l0 = 0.f, l1 = 0.f;
    const float scale = 0.08838834764831845f;   // 1/sqrt(128)
    uint32_t* Pw = Ps + warp * 16 * P_STRIDE;

    for (int j0 = 0; j0 <= q0; j0 += 64) {
        __syncthreads();   // previous tile fully consumed (also covers Q-load ordering)
        const size_t kbase = (size_t)(seq_start + j0) * QKV3 + DIM + h * HD;
        const size_t vbase = kbase + DIM;
        #pragma unroll
        for (int j = 0; j < 16; j++) {
            int i = tid + j * 128;
            int r = i >> 5, dg = (i & 31) << 2;
            float4 kv = *reinterpret_cast<const float4*>(qkv + kbase + (size_t)r * QKV3 + dg);
            uint4 pk;
            pk.x = f2tf32(kv.x); pk.y = f2tf32(kv.y); pk.z = f2tf32(kv.z); pk.w = f2tf32(kv.w);
            *reinterpret_cast<uint4*>(&Ks[r * QK_STRIDE + dg]) = pk;
            float4 vv = *reinterpret_cast<const float4*>(qkv + vbase + (size_t)r * QKV3 + dg);
            uint4 pv;
            pv.x = f2tf32(vv.x); pv.y = f2tf32(vv.y); pv.z = f2tf32(vv.z); pv.w = f2tf32(vv.w);
            *reinterpret_cast<uint4*>(&Vs[r * V_STRIDE + dg]) = pv;
        }
        __syncthreads();

        // S = Q K^T  (warp handles 16 query rows x 64 keys)
        float sacc[8][4];
        #pragma unroll
        for (int nf = 0; nf < 8; nf++)
            #pragma unroll
            for (int e = 0; e < 4; e++) sacc[nf][e] = 0.f;

        #pragma unroll
        for (int ks = 0; ks < 16; ks++) {
            int kk = ks * 8;
            uint32_t af[4];
            int mrow = warp * 16 + lq;
            af[0] = Qs[mrow * QK_STRIDE + kk + lr];
            af[1] = Qs[(mrow + 8) * QK_STRIDE + kk + lr];
            af[2] = Qs[mrow * QK_STRIDE + kk + lr + 4];
            af[3] = Qs[(mrow + 8) * QK_STRIDE + kk + lr + 4];
            #pragma unroll
            for (int nf = 0; nf < 8; nf++) {
                uint32_t bf[2];
                int ncol = nf * 8 + lq;
                bf[0] = Ks[ncol * QK_STRIDE + kk + lr];
                bf[1] = Ks[ncol * QK_STRIDE + kk + lr + 4];
                mma_tf32(sacc[nf], af, bf);
            }
        }

        // online softmax
        const bool diag = (j0 == q0);
        const int qrow0 = q0 + warp * 16 + lq;
        const int qrow1 = qrow0 + 8;
        float mx0 = -1e30f, mx1 = -1e30f;
        #pragma unroll
        for (int nf = 0; nf < 8; nf++) {
            #pragma unroll
            for (int e = 0; e < 4; e++) {
                float s = sacc[nf][e] * scale;
                if (diag) {
                    int kc = j0 + nf * 8 + lr * 2 + (e & 1);
                    int qr = (e < 2) ? qrow0 : qrow1;
                    if (kc > qr) s = -1e30f;
                }
                sacc[nf][e] = s;
            }
            mx0 = fmaxf(mx0, fmaxf(sacc[nf][0], sacc[nf][1]));
            mx1 = fmaxf(mx1, fmaxf(sacc[nf][2], sacc[nf][3]));
        }
        mx0 = fmaxf(mx0, __shfl_xor_sync(0xffffffffu, mx0, 1));
        mx0 = fmaxf(mx0, __shfl_xor_sync(0xffffffffu, mx0, 2));
        mx1 = fmaxf(mx1, __shfl_xor_sync(0xffffffffu, mx1, 1));
        mx1 = fmaxf(mx1, __shfl_xor_sync(0xffffffffu, mx1, 2));

        float mn0 = fmaxf(m0, mx0), mn1 = fmaxf(m1, mx1);
        float c0 = exp2f((m0 - mn0) * LOG2E), c1 = exp2f((m1 - mn1) * LOG2E);
        float s0 = 0.f, s1 = 0.f;
        #pragma unroll
        for (int nf = 0; nf < 8; nf++) {
            float p0 = exp2f((sacc[nf][0] - mn0) * LOG2E);
            float p1 = exp2f((sacc[nf][1] - mn0) * LOG2E);
            float p2 = exp2f((sacc[nf][2] - mn1) * LOG2E);
            float p3 = exp2f((sacc[nf][3] - mn1) * LOG2E);
            s0 += p0 + p1; s1 += p2 + p3;
            int col = nf * 8 + lr * 2;
            Pw[lq * P_STRIDE + col]           = f2tf32(p0);
            Pw[lq * P_STRIDE + col + 1]       = f2tf32(p1);
            Pw[(lq + 8) * P_STRIDE + col]     = f2tf32(p2);
            Pw[(lq + 8) * P_STRIDE + col + 1] = f2tf32(p3);
        }
        s0 += __shfl_xor_sync(0xffffffffu, s0, 1);
        s0 += __shfl_xor_sync(0xffffffffu, s0, 2);
        s1 += __shfl_xor_sync(0xffffffffu, s1, 1);
        s1 += __shfl_xor_sync(0xffffffffu, s1, 2);
        l0 = l0 * c0 + s0;
        l1 = l1 * c1 + s1;
        m0 = mn0; m1 = mn1;
        #pragma unroll
        for (int nf = 0; nf < 16; nf++) {
            oacc[nf][0] *= c0; oacc[nf][1] *= c0;
            oacc[nf][2] *= c1; oacc[nf][3] *= c1;
        }
        __syncwarp();

        // O += P V
        #pragma unroll
        for (int ks = 0; ks < 8; ks++) {
            int kk = ks * 8;
            uint32_t af[4];
            af[0] = Pw[lq * P_STRIDE + kk + lr];
            af[1] = Pw[(lq + 8) * P_STRIDE + kk + lr];
            af[2] = Pw[lq * P_STRIDE + kk + lr + 4];
            af[3] = Pw[(lq + 8) * P_STRIDE + kk + lr + 4];
            #pragma unroll
            for (int nf = 0; nf < 16; nf++) {
                uint32_t bf[2];
                int ncol = nf * 8 + lq;
                bf[0] = Vs[(kk + lr) * V_STRIDE + ncol];
                bf[1] = Vs[(kk + lr + 4) * V_STRIDE + ncol];
                mma_tf32(oacc[nf], af, bf);
            }
        }
        __syncwarp();
    }

    // epilogue
    float inv0 = 1.f / l0, inv1 = 1.f / l1;
    int t0 = seq_start + q0 + warp * 16 + lq;
    float* ob = out + (size_t)t0 * DIM + h * HD;
    #pragma unroll
    for (int nf = 0; nf < 16; nf++) {
        int c = nf * 8 + lr * 2;
        float2 v0 = make_float2(oacc[nf][0] * inv0, oacc[nf][1] * inv0);
        float2 v1 = make_float2(oacc[nf][2] * inv1, oacc[nf][3] * inv1);
        *reinterpret_cast<float2*>(ob + c) = v0;
        *reinterpret_cast<float2*>(ob + (size_t)8 * DIM + c) = v1;
    }
}

// ---------------- sigmoid gate: g = sigmoid(g) * u ----------------
__global__ __launch_bounds__(256) void gate_kernel(float* __restrict__ g,
                                                   const float* __restrict__ u, int n4)
{
    int i = blockIdx.x * blockDim.x + threadIdx.x;
    if (i < n4) {
        float4 gv = reinterpret_cast<const float4*>(g)[i];
        float4 uv = reinterpret_cast<const float4*>(u)[i];
        gv.x = uv.x / (1.f + expf(-gv.x));
        gv.y = uv.y / (1.f + expf(-gv.y));
        gv.z = uv.z / (1.f + expf(-gv.z));
        gv.w = uv.w / (1.f + expf(-gv.w));
        reinterpret_cast<float4*>(g)[i] = gv;
    }
}

// ---------------- launch ----------------
extern "C" void kernel_launch(void* const* d_in, const int* in_sizes, int n_in,
                              void* d_out, int out_size)
{
    const float* hidden     = (const float*)d_in[0];
    const float* ln1_w      = (const float*)d_in[1];
    const float* ln2_w      = (const float*)d_in[2];
    const float* in_proj_w  = (const float*)d_in[3];
    const float* in_proj_b  = (const float*)d_in[4];
    const float* out_proj_w = (const float*)d_in[5];
    const float* out_proj_b = (const float*)d_in[6];
    const float* gate_w     = (const float*)d_in[7];
    const float* up_w       = (const float*)d_in[8];
    const float* down_w     = (const float*)d_in[9];
    float* out = (float*)d_out;

    float *p_ln, *p_qkv, *p_attn, *p_h2, *p_gate, *p_up;
    cudaGetSymbolAddress((void**)&p_ln,   g_ln);
    cudaGetSymbolAddress((void**)&p_qkv,  g_qkv);
    cudaGetSymbolAddress((void**)&p_attn, g_attn);
    cudaGetSymbolAddress((void**)&p_h2,   g_h2);
    cudaGetSymbolAddress((void**)&p_gate, g_gate);
    cudaGetSymbolAddress((void**)&p_up,   g_up);

    const int attn_smem = ATTN_SMEM_WORDS * 4;
    cudaFuncSetAttribute((const void*)attn_kernel,
                         cudaFuncAttributeMaxDynamicSharedMemorySize, attn_smem);

    // 1. rmsnorm1
    rmsnorm_kernel<<<TOTAL, 256>>>(hidden, ln1_w, p_ln);
    // 2. qkv projection
    gemm_tf32_kernel<<<dim3(QKV3 / 128, TOTAL / 128), 256>>>(
        p_ln, in_proj_w, in_proj_b, nullptr, p_qkv, TOTAL, QKV3, DIM);
    // 3. attention
    attn_kernel<<<dim3(144, HEADS), 128, attn_smem>>>(p_qkv, p_attn);
    // 4. out projection + residual
    gemm_tf32_kernel<<<dim3(DIM / 128, TOTAL / 128), 256>>>(
        p_attn, out_proj_w, out_proj_b, hidden, p_h2, TOTAL, DIM, DIM);
    // 5. rmsnorm2
    rmsnorm_kernel<<<TOTAL, 256>>>(p_h2, ln2_w, p_ln);
    // 6/7. gate & up projections
    gemm_tf32_kernel<<<dim3(FDIM / 128, TOTAL / 128), 256>>>(
        p_ln, gate_w, nullptr, nullptr, p_gate, TOTAL, FDIM, DIM);
    gemm_tf32_kernel<<<dim3(FDIM / 128, TOTAL / 128), 256>>>(
        p_ln, up_w, nullptr, nullptr, p_up, TOTAL, FDIM, DIM);
    // 8. sigmoid gate
    int n4 = (TOTAL * FDIM) / 4;
    gate_kernel<<<(n4 + 255) / 256, 256>>>(p_gate, p_up, n4);
    // 9. down projection + residual -> output
    gemm_tf32_kernel<<<dim3(DIM / 128, TOTAL / 128), 256>>>(
        p_gate, down_w, nullptr, p_h2, out, TOTAL, DIM, FDIM);
}

// round 2
// speedup vs baseline: 1.1158x; 1.1158x over previous
#include <cuda_runtime.h>
#include <cstdint>

#define TOTAL   9216
#define DIM     2048
#define HEADS   16
#define HD      128
#define FDIM    8192
#define QKV3    6144

// ---------------- scratch (device globals: allocation-free) ----------------
__device__ float g_ln  [(size_t)TOTAL * DIM];
__device__ float g_qkv [(size_t)TOTAL * QKV3];
__device__ float g_attn[(size_t)TOTAL * DIM];
__device__ float g_h2  [(size_t)TOTAL * DIM];
__device__ float g_gate[(size_t)TOTAL * FDIM];
__device__ float g_up  [(size_t)TOTAL * FDIM];

__device__ const int c_seqlen[8] = {512, 1024, 2048, 768, 1536, 896, 1280, 1152};

// ---------------- helpers ----------------
__device__ __forceinline__ uint32_t f2tf32(float x) {
    uint32_t r;
    asm("cvt.rna.tf32.f32 %0, %1;" : "=r"(r) : "f"(x));
    return r;
}

__device__ __forceinline__ void mma_tf32(float* c, const uint32_t* a, const uint32_t* b) {
    asm("mma.sync.aligned.m16n8k8.row.col.f32.tf32.tf32.f32 "
        "{%0,%1,%2,%3},{%4,%5,%6,%7},{%8,%9},{%0,%1,%2,%3};"
        : "+f"(c[0]), "+f"(c[1]), "+f"(c[2]), "+f"(c[3])
        : "r"(a[0]), "r"(a[1]), "r"(a[2]), "r"(a[3]), "r"(b[0]), "r"(b[1]));
}

__device__ __forceinline__ void cp_async16(void* smem_dst, const void* gmem_src) {
    uint32_t s = (uint32_t)__cvta_generic_to_shared(smem_dst);
    asm volatile("cp.async.cg.shared.global [%0], [%1], 16;" :: "r"(s), "l"(gmem_src));
}
__device__ __forceinline__ void cp_commit() {
    asm volatile("cp.async.commit_group;");
}

// ---------------- RMSNorm ----------------
__global__ __launch_bounds__(256) void rmsnorm_kernel(const float* __restrict__ x,
                                                      const float* __restrict__ w,
                                                      float* __restrict__ y)
{
    int row = blockIdx.x;
    const float4* xr = reinterpret_cast<const float4*>(x + (size_t)row * DIM);
    float4*       yr = reinterpret_cast<float4*>(y + (size_t)row * DIM);
    const float4* wr = reinterpret_cast<const float4*>(w);
    int tid = threadIdx.x;

    float4 v0 = xr[tid];
    float4 v1 = xr[tid + 256];
    float ss = v0.x*v0.x + v0.y*v0.y + v0.z*v0.z + v0.w*v0.w
             + v1.x*v1.x + v1.y*v1.y + v1.z*v1.z + v1.w*v1.w;
    #pragma unroll
    for (int o = 16; o; o >>= 1) ss += __shfl_xor_sync(0xffffffffu, ss, o);

    __shared__ float red[8];
    __shared__ float stot;
    if ((tid & 31) == 0) red[tid >> 5] = ss;
    __syncthreads();
    if (tid == 0) {
        float t = 0.f;
        #pragma unroll
        for (int i = 0; i < 8; i++) t += red[i];
        stot = rsqrtf(t * (1.0f / (float)DIM) + 1e-6f);
    }
    __syncthreads();
    float r = stot;

    float4 w0 = wr[tid], w1 = wr[tid + 256];
    yr[tid]       = make_float4(v0.x*r*w0.x, v0.y*r*w0.y, v0.z*r*w0.z, v0.w*r*w0.w);
    yr[tid + 256] = make_float4(v1.x*r*w1.x, v1.y*r*w1.y, v1.z*r*w1.z, v1.w*r*w1.w);
}

// ---------------- TF32 GEMM with 3-stage cp.async pipeline ----------------
// C[M,N] = A[M,K] * B[N,K]^T (+bias)(+resid). 128x128x32 tile, 256 thr.
#define GSTRIDE 36
#define STAGE_WORDS (2 * 128 * GSTRIDE)   // A + B per stage (float words)
#define GEMM_SMEM_BYTES (3 * STAGE_WORDS * 4)

__global__ __launch_bounds__(256, 2) void gemm_tf32_kernel(
    const float* __restrict__ A, const float* __restrict__ B,
    const float* __restrict__ bias, const float* __restrict__ resid,
    float* __restrict__ C, int M, int N, int K)
{
    extern __shared__ float gsm[];

    const int tid  = threadIdx.x;
    const int lane = tid & 31, warp = tid >> 5;
    const int lq = lane >> 2, lr = lane & 3;
    const int wm = (warp >> 2) * 64, wn = (warp & 3) * 32;
    const int bm = blockIdx.y * 128, bn = blockIdx.x * 128;

    float acc[4][4][4];
    #pragma unroll
    for (int mf = 0; mf < 4; mf++)
        #pragma unroll
        for (int nf = 0; nf < 4; nf++)
            #pragma unroll
            for (int e = 0; e < 4; e++) acc[mf][nf][e] = 0.f;

    const float* Abase = A + (size_t)bm * K;
    const float* Bbase = B + (size_t)bn * K;
    const int ntiles = K >> 5;

    const int ld_r  = tid >> 3;          // 0..31
    const int ld_kg = (tid & 7) << 2;    // 0,4,..,28

    // prologue: stages 0,1,2
    #pragma unroll
    for (int s = 0; s < 3; s++) {
        float* As = gsm + s * STAGE_WORDS;
        float* Bs = As + 128 * GSTRIDE;
        int k0 = s << 5;
        #pragma unroll
        for (int j = 0; j < 4; j++) {
            int r = ld_r + j * 32;
            cp_async16(As + r * GSTRIDE + ld_kg, Abase + (size_t)r * K + k0 + ld_kg);
            cp_async16(Bs + r * GSTRIDE + ld_kg, Bbase + (size_t)r * K + k0 + ld_kg);
        }
        cp_commit();
    }

    for (int i = 0; i < ntiles; i++) {
        asm volatile("cp.async.wait_group 2;");
        __syncthreads();

        int st = i % 3;
        const float* As = gsm + st * STAGE_WORDS;
        const float* Bs = As + 128 * GSTRIDE;

        #pragma unroll
        for (int ks = 0; ks < 4; ks++) {
            int kk = ks * 8;
            uint32_t af[4][4], bf[4][2];
            #pragma unroll
            for (int mf = 0; mf < 4; mf++) {
                int mrow = wm + mf * 16 + lq;
                af[mf][0] = f2tf32(As[mrow * GSTRIDE + kk + lr]);
                af[mf][1] = f2tf32(As[(mrow + 8) * GSTRIDE + kk + lr]);
                af[mf][2] = f2tf32(As[mrow * GSTRIDE + kk + lr + 4]);
                af[mf][3] = f2tf32(As[(mrow + 8) * GSTRIDE + kk + lr + 4]);
            }
            #pragma unroll
            for (int nf = 0; nf < 4; nf++) {
                int ncol = wn + nf * 8 + lq;
                bf[nf][0] = f2tf32(Bs[ncol * GSTRIDE + kk + lr]);
                bf[nf][1] = f2tf32(Bs[ncol * GSTRIDE + kk + lr + 4]);
            }
            #pragma unroll
            for (int mf = 0; mf < 4; mf++)
                #pragma unroll
                for (int nf = 0; nf < 4; nf++)
                    mma_tf32(acc[mf][nf], af[mf], bf[nf]);
        }
        __syncthreads();

        if (i + 3 < ntiles) {
            float* Ad = gsm + st * STAGE_WORDS;
            float* Bd = Ad + 128 * GSTRIDE;
            int k0 = (i + 3) << 5;
            #pragma unroll
            for (int j = 0; j < 4; j++) {
                int r = ld_r + j * 32;
                cp_async16(Ad + r * GSTRIDE + ld_kg, Abase + (size_t)r * K + k0 + ld_kg);
                cp_async16(Bd + r * GSTRIDE + ld_kg, Bbase + (size_t)r * K + k0 + ld_kg);
            }
        }
        cp_commit();
    }

    // epilogue
    #pragma unroll
    for (int mf = 0; mf < 4; mf++) {
        #pragma unroll
        for (int nf = 0; nf < 4; nf++) {
            int r0 = bm + wm + mf * 16 + lq;
            int c0 = bn + wn + nf * 8 + lr * 2;
            float b0 = 0.f, b1 = 0.f;
            if (bias) { b0 = bias[c0]; b1 = bias[c0 + 1]; }
            float2 v0 = make_float2(acc[mf][nf][0] + b0, acc[mf][nf][1] + b1);
            float2 v1 = make_float2(acc[mf][nf][2] + b0, acc[mf][nf][3] + b1);
            if (resid) {
                float2 ra = *reinterpret_cast<const float2*>(resid + (size_t)r0 * N + c0);
                float2 rb = *reinterpret_cast<const float2*>(resid + (size_t)(r0 + 8) * N + c0);
                v0.x += ra.x; v0.y += ra.y;
                v1.x += rb.x; v1.y += rb.y;
            }
            *reinterpret_cast<float2*>(C + (size_t)r0 * N + c0) = v0;
            *reinterpret_cast<float2*>(C + (size_t)(r0 + 8) * N + c0) = v1;
        }
    }
}

// ---------------- Flash attention v2 ----------------
// 256 threads (8 warps), 128-row Q tile, 64-row K/V tiles double-buffered via cp.async.
// Q stored tf32 in smem; K/V raw fp32 (cvt after LDS); P kept in registers (shuffle re-frag).
#define Q_STRIDE 132
#define K_STRIDE 132
#define V_STRIDE 136
#define LOG2E 1.4426950408889634f

#define ATTN_SMEM_BYTES ((128*Q_STRIDE + 2*64*K_STRIDE + 2*64*V_STRIDE) * 4)

__global__ __launch_bounds__(256) void attn_kernel(const float* __restrict__ qkv,
                                                   float* __restrict__ out)
{
    extern __shared__ char asm_base[];
    uint32_t* Qs   = reinterpret_cast<uint32_t*>(asm_base);
    float*    Kraw = reinterpret_cast<float*>(asm_base) + 128 * Q_STRIDE;
    float*    Vraw = Kraw + 2 * 64 * K_STRIDE;

    const int tile = blockIdx.x;   // 0..71 (128-row q tiles)
    const int h    = blockIdx.y;

    int seq_start = 0, q0 = 0, seq_len = 0;
    {
        int acc = 0, start = 0;
        #pragma unroll
        for (int s = 0; s < 8; s++) {
            int nt = c_seqlen[s] >> 7;
            if (tile >= acc && tile < acc + nt) {
                seq_start = start; q0 = (tile - acc) << 7; seq_len = c_seqlen[s];
            }
            acc += nt; start += c_seqlen[s];
        }
    }
    (void)seq_len;

    const int tid = threadIdx.x, lane = tid & 31, warp = tid >> 5;
    const int lq = lane >> 2, lr = lane & 3;
    const int nkv = (q0 >> 6) + 2;

    const size_t kv_row0 = (size_t)seq_start * QKV3 + DIM + (size_t)h * HD;

    // prologue: issue KV tiles 0 and 1
    #pragma unroll
    for (int t = 0; t < 2; t++) {
        float* Kd = Kraw + (t & 1) * (64 * K_STRIDE);
        float* Vd = Vraw + (t & 1) * (64 * V_STRIDE);
        const float* kb = qkv + kv_row0 + (size_t)(t * 64) * QKV3;
        #pragma unroll
        for (int j = 0; j < 8; j++) {
            int i = tid + j * 256;
            int r = i >> 5, dg = (i & 31) << 2;
            cp_async16(Kd + r * K_STRIDE + dg, kb + (size_t)r * QKV3 + dg);
            cp_async16(Vd + r * V_STRIDE + dg, kb + (size_t)r * QKV3 + DIM + dg);
        }
        cp_commit();
    }

    // load Q tile (128 x 128), tf32 in smem
    {
        const size_t qbase = (size_t)(seq_start + q0) * QKV3 + (size_t)h * HD;
        #pragma unroll
        for (int j = 0; j < 16; j++) {
            int i = tid + j * 256;
            int r = i >> 5, dg = (i & 31) << 2;
            float4 v = *reinterpret_cast<const float4*>(qkv + qbase + (size_t)r * QKV3 + dg);
            uint4 p;
            p.x = f2tf32(v.x); p.y = f2tf32(v.y); p.z = f2tf32(v.z); p.w = f2tf32(v.w);
            *reinterpret_cast<uint4*>(&Qs[r * Q_STRIDE + dg]) = p;
        }
    }

    float oacc[16][4];
    #pragma unroll
    for (int nf = 0; nf < 16; nf++)
        #pragma unroll
        for (int e = 0; e < 4; e++) oacc[nf][e] = 0.f;
    float m0 = -1e30f, m1 = -1e30f, l0 = 0.f, l1 = 0.f;
    const float scale = 0.08838834764831845f;   // 1/sqrt(128)

    const int qbase_warp = q0 + warp * 16;       // seq-local first q row of this warp
    const int srcA = (lane & ~3) | (lr >> 1);
    const int srcB = srcA + 2;

    for (int t = 0; t < nkv; t++) {
        asm volatile("cp.async.wait_group 1;");
        __syncthreads();

        const int j0 = t << 6;
        const float* Kb = Kraw + (t & 1) * (64 * K_STRIDE);
        const float* Vb = Vraw + (t & 1) * (64 * V_STRIDE);
        const bool skipw = (j0 > qbase_warp + 15);

        if (!skipw) {
            // ---- S = Q K^T : warp's 16 rows x 64 keys ----
            float sacc[8][4];
            #pragma unroll
            for (int nf = 0; nf < 8; nf++)
                #pragma unroll
                for (int e = 0; e < 4; e++) sacc[nf][e] = 0.f;

            #pragma unroll
            for (int ks = 0; ks < 16; ks++) {
                int kk = ks * 8;
                uint32_t af[4];
                int mrow = warp * 16 + lq;
                af[0] = Qs[mrow * Q_STRIDE + kk + lr];
                af[1] = Qs[(mrow + 8) * Q_STRIDE + kk + lr];
                af[2] = Qs[mrow * Q_STRIDE + kk + lr + 4];
                af[3] = Qs[(mrow + 8) * Q_STRIDE + kk + lr + 4];
                #pragma unroll
                for (int nf = 0; nf < 8; nf++) {
                    uint32_t bf[2];
                    int ncol = nf * 8 + lq;
                    bf[0] = f2tf32(Kb[ncol * K_STRIDE + kk + lr]);
                    bf[1] = f2tf32(Kb[ncol * K_STRIDE + kk + lr + 4]);
                    mma_tf32(sacc[nf], af, bf);
                }
            }

            // ---- online softmax ----
            const bool diag = (j0 + 63 > qbase_warp);
            const int qr0 = qbase_warp + lq;
            const int qr1 = qr0 + 8;
            float mx0 = -1e30f, mx1 = -1e30f;
            #pragma unroll
            for (int nf = 0; nf < 8; nf++) {
                #pragma unroll
                for (int e = 0; e < 4; e++) {
                    float s = sacc[nf][e] * scale;
                    if (diag) {
                        int kc = j0 + nf * 8 + lr * 2 + (e & 1);
                        int qr = (e < 2) ? qr0 : qr1;
                        if (kc > qr) s = -1e30f;
                    }
                    sacc[nf][e] = s;
                }
                mx0 = fmaxf(mx0, fmaxf(sacc[nf][0], sacc[nf][1]));
                mx1 = fmaxf(mx1, fmaxf(sacc[nf][2], sacc[nf][3]));
            }
            mx0 = fmaxf(mx0, __shfl_xor_sync(0xffffffffu, mx0, 1));
            mx0 = fmaxf(mx0, __shfl_xor_sync(0xffffffffu, mx0, 2));
            mx1 = fmaxf(mx1, __shfl_xor_sync(0xffffffffu, mx1, 1));
            mx1 = fmaxf(mx1, __shfl_xor_sync(0xffffffffu, mx1, 2));

            float mn0 = fmaxf(m0, mx0), mn1 = fmaxf(m1, mx1);
            float c0 = exp2f((m0 - mn0) * LOG2E), c1 = exp2f((m1 - mn1) * LOG2E);
            float s0 = 0.f, s1 = 0.f;
            uint32_t pk[8][4];
            #pragma unroll
            for (int nf = 0; nf < 8; nf++) {
                float p0 = exp2f((sacc[nf][0] - mn0) * LOG2E);
                float p1 = exp2f((sacc[nf][1] - mn0) * LOG2E);
                float p2 = exp2f((sacc[nf][2] - mn1) * LOG2E);
                float p3 = exp2f((sacc[nf][3] - mn1) * LOG2E);
                s0 += p0 + p1; s1 += p2 + p3;
                pk[nf][0] = f2tf32(p0);
                pk[nf][1] = f2tf32(p1);
                pk[nf][2] = f2tf32(p2);
                pk[nf][3] = f2tf32(p3);
            }
            s0 += __shfl_xor_sync(0xffffffffu, s0, 1);
            s0 += __shfl_xor_sync(0xffffffffu, s0, 2);
            s1 += __shfl_xor_sync(0xffffffffu, s1, 1);
            s1 += __shfl_xor_sync(0xffffffffu, s1, 2);
            l0 = l0 * c0 + s0;
            l1 = l1 * c1 + s1;
            m0 = mn0; m1 = mn1;
            #pragma unroll
            for (int nf = 0; nf < 16; nf++) {
                oacc[nf][0] *= c0; oacc[nf][1] *= c0;
                oacc[nf][2] *= c1; oacc[nf][3] *= c1;
            }

            // ---- O += P V (P re-fragmented via shuffles) ----
            #pragma unroll
            for (int ks = 0; ks < 8; ks++) {
                uint32_t af[4];
                {
                    uint32_t u0 = __shfl_sync(0xffffffffu, pk[ks][0], srcA);
                    uint32_t u1 = __shfl_sync(0xffffffffu, pk[ks][1], srcA);
                    uint32_t u2 = __shfl_sync(0xffffffffu, pk[ks][2], srcA);
                    uint32_t u3 = __shfl_sync(0xffffffffu, pk[ks][3], srcA);
                    uint32_t v0 = __shfl_sync(0xffffffffu, pk[ks][0], srcB);
                    uint32_t v1 = __shfl_sync(0xffffffffu, pk[ks][1], srcB);
                    uint32_t v2 = __shfl_sync(0xffffffffu, pk[ks][2], srcB);
                    uint32_t v3 = __shfl_sync(0xffffffffu, pk[ks][3], srcB);
                    af[0] = (lr & 1) ? u1 : u0;
                    af[1] = (lr & 1) ? u3 : u2;
                    af[2] = (lr & 1) ? v1 : v0;
                    af[3] = (lr & 1) ? v3 : v2;
                }
                int kk = ks * 8;
                #pragma unroll
                for (int nf = 0; nf < 16; nf++) {
                    uint32_t bf[2];
                    int ncol = nf * 8 + lq;
                    bf[0] = f2tf32(Vb[(kk + lr) * V_STRIDE + ncol]);
                    bf[1] = f2tf32(Vb[(kk + lr + 4) * V_STRIDE + ncol]);
                    mma_tf32(oacc[nf], af, bf);
                }
            }
        }

        __syncthreads();

        // issue tile t+2 into the buffer we just finished reading
        if (t + 2 < nkv) {
            float* Kd = Kraw + (t & 1) * (64 * K_STRIDE);
            float* Vd = Vraw + (t & 1) * (64 * V_STRIDE);
            const float* kb = qkv + kv_row0 + (size_t)((t + 2) * 64) * QKV3;
            #pragma unroll
            for (int j = 0; j < 8; j++) {
                int i = tid + j * 256;
                int r = i >> 5, dg = (i & 31) << 2;
                cp_async16(Kd + r * K_STRIDE + dg, kb + (size_t)r * QKV3 + dg);
                cp_async16(Vd + r * V_STRIDE + dg, kb + (size_t)r * QKV3 + DIM + dg);
            }
        }
        cp_commit();
    }

    // epilogue
    float inv0 = 1.f / l0, inv1 = 1.f / l1;
    int t0 = seq_start + q0 + warp * 16 + lq;
    float* ob = out + (size_t)t0 * DIM + (size_t)h * HD;
    #pragma unroll
    for (int nf = 0; nf < 16; nf++) {
        int c = nf * 8 + lr * 2;
        *reinterpret_cast<float2*>(ob + c) =
            make_float2(oacc[nf][0] * inv0, oacc[nf][1] * inv0);
        *reinterpret_cast<float2*>(ob + (size_t)8 * DIM + c) =
            make_float2(oacc[nf][2] * inv1, oacc[nf][3] * inv1);
    }
}

// ---------------- sigmoid gate: g = sigmoid(g) * u ----------------
__global__ __launch_bounds__(256) void gate_kernel(float* __restrict__ g,
                                                   const float* __restrict__ u, int n4)
{
    int i = blockIdx.x * blockDim.x + threadIdx.x;
    if (i < n4) {
        float4 gv = reinterpret_cast<const float4*>(g)[i];
        float4 uv = reinterpret_cast<const float4*>(u)[i];
        gv.x = uv.x / (1.f + __expf(-gv.x));
        gv.y = uv.y / (1.f + __expf(-gv.y));
        gv.z = uv.z / (1.f + __expf(-gv.z));
        gv.w = uv.w / (1.f + __expf(-gv.w));
        reinterpret_cast<float4*>(g)[i] = gv;
    }
}

// ---------------- launch ----------------
extern "C" void kernel_launch(void* const* d_in, const int* in_sizes, int n_in,
                              void* d_out, int out_size)
{
    const float* hidden     = (const float*)d_in[0];
    const float* ln1_w      = (const float*)d_in[1];
    const float* ln2_w      = (const float*)d_in[2];
    const float* in_proj_w  = (const float*)d_in[3];
    const float* in_proj_b  = (const float*)d_in[4];
    const float* out_proj_w = (const float*)d_in[5];
    const float* out_proj_b = (const float*)d_in[6];
    const float* gate_w     = (const float*)d_in[7];
    const float* up_w       = (const float*)d_in[8];
    const float* down_w     = (const float*)d_in[9];
    float* out = (float*)d_out;

    float *p_ln, *p_qkv, *p_attn, *p_h2, *p_gate, *p_up;
    cudaGetSymbolAddress((void**)&p_ln,   g_ln);
    cudaGetSymbolAddress((void**)&p_qkv,  g_qkv);
    cudaGetSymbolAddress((void**)&p_attn, g_attn);
    cudaGetSymbolAddress((void**)&p_h2,   g_h2);
    cudaGetSymbolAddress((void**)&p_gate, g_gate);
    cudaGetSymbolAddress((void**)&p_up,   g_up);

    cudaFuncSetAttribute((const void*)gemm_tf32_kernel,
                         cudaFuncAttributeMaxDynamicSharedMemorySize, GEMM_SMEM_BYTES);
    cudaFuncSetAttribute((const void*)attn_kernel,
                         cudaFuncAttributeMaxDynamicSharedMemorySize, ATTN_SMEM_BYTES);

    // 1. rmsnorm1
    rmsnorm_kernel<<<TOTAL, 256>>>(hidden, ln1_w, p_ln);
    // 2. qkv projection
    gemm_tf32_kernel<<<dim3(QKV3 / 128, TOTAL / 128), 256, GEMM_SMEM_BYTES>>>(
        p_ln, in_proj_w, in_proj_b, nullptr, p_qkv, TOTAL, QKV3, DIM);
    // 3. attention
    attn_kernel<<<dim3(TOTAL / 128, HEADS), 256, ATTN_SMEM_BYTES>>>(p_qkv, p_attn);
    // 4. out projection + residual
    gemm_tf32_kernel<<<dim3(DIM / 128, TOTAL / 128), 256, GEMM_SMEM_BYTES>>>(
        p_attn, out_proj_w, out_proj_b, hidden, p_h2, TOTAL, DIM, DIM);
    // 5. rmsnorm2
    rmsnorm_kernel<<<TOTAL, 256>>>(p_h2, ln2_w, p_ln);
    // 6/7. gate & up projections
    gemm_tf32_kernel<<<dim3(FDIM / 128, TOTAL / 128), 256, GEMM_SMEM_BYTES>>>(
        p_ln, gate_w, nullptr, nullptr, p_gate, TOTAL, FDIM, DIM);
    gemm_tf32_kernel<<<dim3(FDIM / 128, TOTAL / 128), 256, GEMM_SMEM_BYTES>>>(
        p_ln, up_w, nullptr, nullptr, p_up, TOTAL, FDIM, DIM);
    // 8. sigmoid gate
    int n4 = (TOTAL * FDIM) / 4;
    gate_kernel<<<(n4 + 255) / 256, 256>>>(p_gate, p_up, n4);
    // 9. down projection + residual -> output
    gemm_tf32_kernel<<<dim3(DIM / 128, TOTAL / 128), 256, GEMM_SMEM_BYTES>>>(
        p_gate, down_w, nullptr, p_h2, out, TOTAL, DIM, FDIM);
}

// round 5
// speedup vs baseline: 2.1082x; 1.8894x over previous
#include <cuda_runtime.h>
#include <cuda_fp16.h>
#include <cstdint>

#define TOTAL   9216
#define DIM     2048
#define HEADS   16
#define HD      128
#define FDIM    8192
#define QKV3    6144

// ---------------- scratch (device globals: allocation-free) ----------------
__device__ __half g_ln  [(size_t)TOTAL * DIM];
__device__ float  g_qkv [(size_t)TOTAL * QKV3];
__device__ __half g_attn[(size_t)TOTAL * DIM];
__device__ float  g_h2  [(size_t)TOTAL * DIM];
__device__ __half g_gate[(size_t)TOTAL * FDIM];
__device__ __half g_up  [(size_t)TOTAL * FDIM];
// fp16 weight copies
__device__ __half g_wqkv [(size_t)QKV3 * DIM];
__device__ __half g_wout [(size_t)DIM * DIM];
__device__ __half g_wgate[(size_t)FDIM * DIM];
__device__ __half g_wup  [(size_t)FDIM * DIM];
__device__ __half g_wdown[(size_t)DIM * FDIM];

__device__ const int c_seqlen[8] = {512, 1024, 2048, 768, 1536, 896, 1280, 1152};

// ---------------- helpers ----------------
__device__ __forceinline__ uint32_t f2tf32(float x) {
    uint32_t r;
    asm("cvt.rna.tf32.f32 %0, %1;" : "=r"(r) : "f"(x));
    return r;
}

__device__ __forceinline__ void mma_tf32(float* c, const uint32_t* a, const uint32_t* b) {
    asm("mma.sync.aligned.m16n8k8.row.col.f32.tf32.tf32.f32 "
        "{%0,%1,%2,%3},{%4,%5,%6,%7},{%8,%9},{%0,%1,%2,%3};"
        : "+f"(c[0]), "+f"(c[1]), "+f"(c[2]), "+f"(c[3])
        : "r"(a[0]), "r"(a[1]), "r"(a[2]), "r"(a[3]), "r"(b[0]), "r"(b[1]));
}

__device__ __forceinline__ void mma_f16(float* c, const uint32_t* a, const uint32_t* b) {
    asm("mma.sync.aligned.m16n8k16.row.col.f32.f16.f16.f32 "
        "{%0,%1,%2,%3},{%4,%5,%6,%7},{%8,%9},{%0,%1,%2,%3};"
        : "+f"(c[0]), "+f"(c[1]), "+f"(c[2]), "+f"(c[3])
        : "r"(a[0]), "r"(a[1]), "r"(a[2]), "r"(a[3]), "r"(b[0]), "r"(b[1]));
}

__device__ __forceinline__ void cp_async16(void* smem_dst, const void* gmem_src) {
    uint32_t s = (uint32_t)__cvta_generic_to_shared(smem_dst);
    asm volatile("cp.async.cg.shared.global [%0], [%1], 16;" :: "r"(s), "l"(gmem_src));
}
__device__ __forceinline__ void cp_commit() {
    asm volatile("cp.async.commit_group;");
}

// ================= fp16 GEMM =================
// C[M,N] = A[M,K] * B[N,K]^T (+bias)(+resid), A,B fp16, accum fp32.
// 128x128 tile, 256 threads (8 warps as 2x4, warp tile 64x32), K-chunk 64,
// 3-stage cp.async pipeline. Smem stride 72 halves: conflict-free frag LDS.
#define HSTRIDE 72
#define A_HALFS (128 * HSTRIDE)
#define STAGE_HALFS (2 * A_HALFS)
#define GEMM_SMEM_BYTES (3 * STAGE_HALFS * 2)

__device__ __forceinline__ void h_load_stage(const __half* __restrict__ Ab,
                                             const __half* __restrict__ Bb,
                                             int K, __half* As, __half* Bs, int tid)
{
    #pragma unroll
    for (int j = 0; j < 4; j++) {
        int id = tid + j * 256;
        int r = id >> 3, g = (id & 7) << 3;     // 8 halves = 16B per group
        cp_async16(As + r * HSTRIDE + g, Ab + (size_t)r * K + g);
        cp_async16(Bs + r * HSTRIDE + g, Bb + (size_t)r * K + g);
    }
}

__global__ __launch_bounds__(256, 2) void gemm_f16_kernel(
    const __half* __restrict__ A, const __half* __restrict__ B,
    const float* __restrict__ bias, const float* __restrict__ resid,
    float* __restrict__ Cf, __half* __restrict__ Ch, int M, int N, int K)
{
    extern __shared__ __half hsm[];

    const int tid  = threadIdx.x;
    const int lane = tid & 31, warp = tid >> 5;
    const int lq = lane >> 2, lr = lane & 3;
    const int wm = (warp >> 2) * 64, wn = (warp & 3) * 32;
    const int bm = blockIdx.y * 128, bn = blockIdx.x * 128;

    float acc[4][4][4];
    #pragma unroll
    for (int mf = 0; mf < 4; mf++)
        #pragma unroll
        for (int nf = 0; nf < 4; nf++)
            #pragma unroll
            for (int e = 0; e < 4; e++) acc[mf][nf][e] = 0.f;

    const __half* Abase = A + (size_t)bm * K;
    const __half* Bbase = B + (size_t)bn * K;
    const int nk = K >> 6;

    // prologue: stages 0,1,2
    #pragma unroll
    for (int s = 0; s < 3; s++) {
        __half* As = hsm + s * STAGE_HALFS;
        __half* Bs = As + A_HALFS;
        h_load_stage(Abase + s * 64, Bbase + s * 64, K, As, Bs, tid);
        cp_commit();
    }

    for (int i = 0; i < nk; i++) {
        asm volatile("cp.async.wait_group 2;");
        __syncthreads();

        int st = i % 3;
        const __half* As = hsm + st * STAGE_HALFS;
        const __half* Bs = As + A_HALFS;

        #pragma unroll
        for (int ks = 0; ks < 4; ks++) {
            int kk = ks * 16;
            uint32_t af[4][4], bf[4][2];
            #pragma unroll
            for (int mf = 0; mf < 4; mf++) {
                int mrow = wm + mf * 16 + lq;
                af[mf][0] = *reinterpret_cast<const uint32_t*>(&As[mrow * HSTRIDE + kk + 2 * lr]);
                af[mf][1] = *reinterpret_cast<const uint32_t*>(&As[(mrow + 8) * HSTRIDE + kk + 2 * lr]);
                af[mf][2] = *reinterpret_cast<const uint32_t*>(&As[mrow * HSTRIDE + kk + 2 * lr + 8]);
                af[mf][3] = *reinterpret_cast<const uint32_t*>(&As[(mrow + 8) * HSTRIDE + kk + 2 * lr + 8]);
            }
            #pragma unroll
            for (int nf = 0; nf < 4; nf++) {
                int ncol = wn + nf * 8 + lq;
                bf[nf][0] = *reinterpret_cast<const uint32_t*>(&Bs[ncol * HSTRIDE + kk + 2 * lr]);
                bf[nf][1] = *reinterpret_cast<const uint32_t*>(&Bs[ncol * HSTRIDE + kk + 2 * lr + 8]);
            }
            #pragma unroll
            for (int mf = 0; mf < 4; mf++)
                #pragma unroll
                for (int nf = 0; nf < 4; nf++)
                    mma_f16(acc[mf][nf], af[mf], bf[nf]);
        }
        __syncthreads();

        if (i + 3 < nk) {
            __half* Ad = hsm + st * STAGE_HALFS;
            __half* Bd = Ad + A_HALFS;
            h_load_stage(Abase + (i + 3) * 64, Bbase + (i + 3) * 64, K, Ad, Bd, tid);
        }
        cp_commit();
    }

    // epilogue
    #pragma unroll
    for (int mf = 0; mf < 4; mf++) {
        #pragma unroll
        for (int nf = 0; nf < 4; nf++) {
            int r0 = bm + wm + mf * 16 + lq;
            int c0 = bn + wn + nf * 8 + lr * 2;
            float b0 = 0.f, b1 = 0.f;
            if (bias) { b0 = bias[c0]; b1 = bias[c0 + 1]; }
            float2 v0 = make_float2(acc[mf][nf][0] + b0, acc[mf][nf][1] + b1);
            float2 v1 = make_float2(acc[mf][nf][2] + b0, acc[mf][nf][3] + b1);
            if (resid) {
                float2 ra = *reinterpret_cast<const float2*>(resid + (size_t)r0 * N + c0);
                float2 rb = *reinterpret_cast<const float2*>(resid + (size_t)(r0 + 8) * N + c0);
                v0.x += ra.x; v0.y += ra.y;
                v1.x += rb.x; v1.y += rb.y;
            }
            if (Ch) {
                *reinterpret_cast<__half2*>(Ch + (size_t)r0 * N + c0) =
                    __floats2half2_rn(v0.x, v0.y);
                *reinterpret_cast<__half2*>(Ch + (size_t)(r0 + 8) * N + c0) =
                    __floats2half2_rn(v1.x, v1.y);
            } else {
                *reinterpret_cast<float2*>(Cf + (size_t)r0 * N + c0) = v0;
                *reinterpret_cast<float2*>(Cf + (size_t)(r0 + 8) * N + c0) = v1;
            }
        }
    }
}

// ---------------- weight convert: fp32 -> fp16 ----------------
__global__ __launch_bounds__(256) void cvtw_kernel(const float4* __restrict__ in,
                                                   __half2* __restrict__ out, int n4)
{
    int i = blockIdx.x * blockDim.x + threadIdx.x;
    if (i < n4) {
        float4 v = in[i];
        out[2 * i]     = __floats2half2_rn(v.x, v.y);
        out[2 * i + 1] = __floats2half2_rn(v.z, v.w);
    }
}

// ---------------- RMSNorm (fp32 in, fp16 out) ----------------
__global__ __launch_bounds__(256) void rmsnorm_kernel(const float* __restrict__ x,
                                                      const float* __restrict__ w,
                                                      __half* __restrict__ y)
{
    int row = blockIdx.x;
    const float4* xr = reinterpret_cast<const float4*>(x + (size_t)row * DIM);
    __half2*      yr = reinterpret_cast<__half2*>(y + (size_t)row * DIM);
    const float4* wr = reinterpret_cast<const float4*>(w);
    int tid = threadIdx.x;

    float4 v0 = xr[tid];
    float4 v1 = xr[tid + 256];
    float ss = v0.x*v0.x + v0.y*v0.y + v0.z*v0.z + v0.w*v0.w
             + v1.x*v1.x + v1.y*v1.y + v1.z*v1.z + v1.w*v1.w;
    #pragma unroll
    for (int o = 16; o; o >>= 1) ss += __shfl_xor_sync(0xffffffffu, ss, o);

    __shared__ float red[8];
    __shared__ float stot;
    if ((tid & 31) == 0) red[tid >> 5] = ss;
    __syncthreads();
    if (tid == 0) {
        float t = 0.f;
        #pragma unroll
        for (int i = 0; i < 8; i++) t += red[i];
        stot = rsqrtf(t * (1.0f / (float)DIM) + 1e-6f);
    }
    __syncthreads();
    float r = stot;

    float4 w0 = wr[tid], w1 = wr[tid + 256];
    yr[2 * tid]             = __floats2half2_rn(v0.x*r*w0.x, v0.y*r*w0.y);
    yr[2 * tid + 1]         = __floats2half2_rn(v0.z*r*w0.z, v0.w*r*w0.w);
    yr[2 * (tid + 256)]     = __floats2half2_rn(v1.x*r*w1.x, v1.y*r*w1.y);
    yr[2 * (tid + 256) + 1] = __floats2half2_rn(v1.z*r*w1.z, v1.w*r*w1.w);
}

// ---------------- Flash attention (tf32 mma; qkv fp32 in, fp16 out) ----------------
#define Q_STRIDE 132
#define K_STRIDE 132
#define V_STRIDE 136
#define LOG2E 1.4426950408889634f

#define ATTN_SMEM_BYTES ((128*Q_STRIDE + 2*64*K_STRIDE + 2*64*V_STRIDE) * 4)

__global__ __launch_bounds__(256) void attn_kernel(const float* __restrict__ qkv,
                                                   __half* __restrict__ out)
{
    extern __shared__ char asm_base[];
    uint32_t* Qs   = reinterpret_cast<uint32_t*>(asm_base);
    float*    Kraw = reinterpret_cast<float*>(asm_base) + 128 * Q_STRIDE;
    float*    Vraw = Kraw + 2 * 64 * K_STRIDE;

    const int tile = blockIdx.x;
    const int h    = blockIdx.y;

    int seq_start = 0, q0 = 0;
    {
        int acc = 0, start = 0;
        #pragma unroll
        for (int s = 0; s < 8; s++) {
            int nt = c_seqlen[s] >> 7;
            if (tile >= acc && tile < acc + nt) {
                seq_start = start; q0 = (tile - acc) << 7;
            }
            acc += nt; start += c_seqlen[s];
        }
    }

    const int tid = threadIdx.x, lane = tid & 31, warp = tid >> 5;
    const int lq = lane >> 2, lr = lane & 3;
    const int nkv = (q0 >> 6) + 2;

    const size_t kv_row0 = (size_t)seq_start * QKV3 + DIM + (size_t)h * HD;

    #pragma unroll
    for (int t = 0; t < 2; t++) {
        float* Kd = Kraw + (t & 1) * (64 * K_STRIDE);
        float* Vd = Vraw + (t & 1) * (64 * V_STRIDE);
        const float* kb = qkv + kv_row0 + (size_t)(t * 64) * QKV3;
        #pragma unroll
        for (int j = 0; j < 8; j++) {
            int i = tid + j * 256;
            int r = i >> 5, dg = (i & 31) << 2;
            cp_async16(Kd + r * K_STRIDE + dg, kb + (size_t)r * QKV3 + dg);
            cp_async16(Vd + r * V_STRIDE + dg, kb + (size_t)r * QKV3 + DIM + dg);
        }
        cp_commit();
    }

    {
        const size_t qbase = (size_t)(seq_start + q0) * QKV3 + (size_t)h * HD;
        #pragma unroll
        for (int j = 0; j < 16; j++) {
            int i = tid + j * 256;
            int r = i >> 5, dg = (i & 31) << 2;
            float4 v = *reinterpret_cast<const float4*>(qkv + qbase + (size_t)r * QKV3 + dg);
            uint4 p;
            p.x = f2tf32(v.x); p.y = f2tf32(v.y); p.z = f2tf32(v.z); p.w = f2tf32(v.w);
            *reinterpret_cast<uint4*>(&Qs[r * Q_STRIDE + dg]) = p;
        }
    }

    float oacc[16][4];
    #pragma unroll
    for (int nf = 0; nf < 16; nf++)
        #pragma unroll
        for (int e = 0; e < 4; e++) oacc[nf][e] = 0.f;
    float m0 = -1e30f, m1 = -1e30f, l0 = 0.f, l1 = 0.f;
    const float scale = 0.08838834764831845f;

    const int qbase_warp = q0 + warp * 16;
    const int srcA = (lane & ~3) | (lr >> 1);
    const int srcB = srcA + 2;

    for (int t = 0; t < nkv; t++) {
        asm volatile("cp.async.wait_group 1;");
        __syncthreads();

        const int j0 = t << 6;
        const float* Kb = Kraw + (t & 1) * (64 * K_STRIDE);
        const float* Vb = Vraw + (t & 1) * (64 * V_STRIDE);
        const bool skipw = (j0 > qbase_warp + 15);

        if (!skipw) {
            float sacc[8][4];
            #pragma unroll
            for (int nf = 0; nf < 8; nf++)
                #pragma unroll
                for (int e = 0; e < 4; e++) sacc[nf][e] = 0.f;

            #pragma unroll
            for (int ks = 0; ks < 16; ks++) {
                int kk = ks * 8;
                uint32_t af[4];
                int mrow = warp * 16 + lq;
                af[0] = Qs[mrow * Q_STRIDE + kk + lr];
                af[1] = Qs[(mrow + 8) * Q_STRIDE + kk + lr];
                af[2] = Qs[mrow * Q_STRIDE + kk + lr + 4];
                af[3] = Qs[(mrow + 8) * Q_STRIDE + kk + lr + 4];
                #pragma unroll
                for (int nf = 0; nf < 8; nf++) {
                    uint32_t bf[2];
                    int ncol = nf * 8 + lq;
                    bf[0] = f2tf32(Kb[ncol * K_STRIDE + kk + lr]);
                    bf[1] = f2tf32(Kb[ncol * K_STRIDE + kk + lr + 4]);
                    mma_tf32(sacc[nf], af, bf);
                }
            }

            const bool diag = (j0 + 63 > qbase_warp);
            const int qr0 = qbase_warp + lq;
            const int qr1 = qr0 + 8;
            float mx0 = -1e30f, mx1 = -1e30f;
            #pragma unroll
            for (int nf = 0; nf < 8; nf++) {
                #pragma unroll
                for (int e = 0; e < 4; e++) {
                    float s = sacc[nf][e] * scale;
                    if (diag) {
                        int kc = j0 + nf * 8 + lr * 2 + (e & 1);
                        int qr = (e < 2) ? qr0 : qr1;
                        if (kc > qr) s = -1e30f;
                    }
                    sacc[nf][e] = s;
                }
                mx0 = fmaxf(mx0, fmaxf(sacc[nf][0], sacc[nf][1]));
                mx1 = fmaxf(mx1, fmaxf(sacc[nf][2], sacc[nf][3]));
            }
            mx0 = fmaxf(mx0, __shfl_xor_sync(0xffffffffu, mx0, 1));
            mx0 = fmaxf(mx0, __shfl_xor_sync(0xffffffffu, mx0, 2));
            mx1 = fmaxf(mx1, __shfl_xor_sync(0xffffffffu, mx1, 1));
            mx1 = fmaxf(mx1, __shfl_xor_sync(0xffffffffu, mx1, 2));

            float mn0 = fmaxf(m0, mx0), mn1 = fmaxf(m1, mx1);
            float c0 = exp2f((m0 - mn0) * LOG2E), c1 = exp2f((m1 - mn1) * LOG2E);
            float s0 = 0.f, s1 = 0.f;
            uint32_t pk[8][4];
            #pragma unroll
            for (int nf = 0; nf < 8; nf++) {
                float p0 = exp2f((sacc[nf][0] - mn0) * LOG2E);
                float p1 = exp2f((sacc[nf][1] - mn0) * LOG2E);
                float p2 = exp2f((sacc[nf][2] - mn1) * LOG2E);
                float p3 = exp2f((sacc[nf][3] - mn1) * LOG2E);
                s0 += p0 + p1; s1 += p2 + p3;
                pk[nf][0] = f2tf32(p0);
                pk[nf][1] = f2tf32(p1);
                pk[nf][2] = f2tf32(p2);
                pk[nf][3] = f2tf32(p3);
            }
            s0 += __shfl_xor_sync(0xffffffffu, s0, 1);
            s0 += __shfl_xor_sync(0xffffffffu, s0, 2);
            s1 += __shfl_xor_sync(0xffffffffu, s1, 1);
            s1 += __shfl_xor_sync(0xffffffffu, s1, 2);
            l0 = l0 * c0 + s0;
            l1 = l1 * c1 + s1;
            m0 = mn0; m1 = mn1;
            #pragma unroll
            for (int nf = 0; nf < 16; nf++) {
                oacc[nf][0] *= c0; oacc[nf][1] *= c0;
                oacc[nf][2] *= c1; oacc[nf][3] *= c1;
            }

            #pragma unroll
            for (int ks = 0; ks < 8; ks++) {
                uint32_t af[4];
                {
                    uint32_t u0 = __shfl_sync(0xffffffffu, pk[ks][0], srcA);
                    uint32_t u1 = __shfl_sync(0xffffffffu, pk[ks][1], srcA);
                    uint32_t u2 = __shfl_sync(0xffffffffu, pk[ks][2], srcA);
                    uint32_t u3 = __shfl_sync(0xffffffffu, pk[ks][3], srcA);
                    uint32_t v0 = __shfl_sync(0xffffffffu, pk[ks][0], srcB);
                    uint32_t v1 = __shfl_sync(0xffffffffu, pk[ks][1], srcB);
                    uint32_t v2 = __shfl_sync(0xffffffffu, pk[ks][2], srcB);
                    uint32_t v3 = __shfl_sync(0xffffffffu, pk[ks][3], srcB);
                    af[0] = (lr & 1) ? u1 : u0;
                    af[1] = (lr & 1) ? u3 : u2;
                    af[2] = (lr & 1) ? v1 : v0;
                    af[3] = (lr & 1) ? v3 : v2;
                }
                int kk = ks * 8;
                #pragma unroll
                for (int nf = 0; nf < 16; nf++) {
                    uint32_t bf[2];
                    int ncol = nf * 8 + lq;
                    bf[0] = f2tf32(Vb[(kk + lr) * V_STRIDE + ncol]);
                    bf[1] = f2tf32(Vb[(kk + lr + 4) * V_STRIDE + ncol]);
                    mma_tf32(oacc[nf], af, bf);
                }
            }
        }

        __syncthreads();

        if (t + 2 < nkv) {
            float* Kd = Kraw + (t & 1) * (64 * K_STRIDE);
            float* Vd = Vraw + (t & 1) * (64 * V_STRIDE);
            const float* kb = qkv + kv_row0 + (size_t)((t + 2) * 64) * QKV3;
            #pragma unroll
            for (int j = 0; j < 8; j++) {
                int i = tid + j * 256;
                int r = i >> 5, dg = (i & 31) << 2;
                cp_async16(Kd + r * K_STRIDE + dg, kb + (size_t)r * QKV3 + dg);
                cp_async16(Vd + r * V_STRIDE + dg, kb + (size_t)r * QKV3 + DIM + dg);
            }
        }
        cp_commit();
    }

    // epilogue -> fp16 (feeds out_proj fp16 GEMM)
    float inv0 = 1.f / l0, inv1 = 1.f / l1;
    int t0 = seq_start + q0 + warp * 16 + lq;
    __half* ob = out + (size_t)t0 * DIM + (size_t)h * HD;
    #pragma unroll
    for (int nf = 0; nf < 16; nf++) {
        int c = nf * 8 + lr * 2;
        *reinterpret_cast<__half2*>(ob + c) =
            __floats2half2_rn(oacc[nf][0] * inv0, oacc[nf][1] * inv0);
        *reinterpret_cast<__half2*>(ob + (size_t)8 * DIM + c) =
            __floats2half2_rn(oacc[nf][2] * inv1, oacc[nf][3] * inv1);
    }
}

// ---------------- sigmoid gate: g = fp16(sigmoid(g) * u) ----------------
__global__ __launch_bounds__(256) void gate_kernel(__half2* __restrict__ g,
                                                   const __half2* __restrict__ u, int n2)
{
    int i = blockIdx.x * blockDim.x + threadIdx.x;
    if (i < n2) {
        float2 gv = __half22float2(g[i]);
        float2 uv = __half22float2(u[i]);
        gv.x = uv.x / (1.f + __expf(-gv.x));
        gv.y = uv.y / (1.f + __expf(-gv.y));
        g[i] = __floats2half2_rn(gv.x, gv.y);
    }
}

// ---------------- launch ----------------
extern "C" void kernel_launch(void* const* d_in, const int* in_sizes, int n_in,
                              void* d_out, int out_size)
{
    const float* hidden     = (const float*)d_in[0];
    const float* ln1_w      = (const float*)d_in[1];
    const float* ln2_w      = (const float*)d_in[2];
    const float* in_proj_w  = (const float*)d_in[3];
    const float* in_proj_b  = (const float*)d_in[4];
    const float* out_proj_w = (const float*)d_in[5];
    const float* out_proj_b = (const float*)d_in[6];
    const float* gate_w     = (const float*)d_in[7];
    const float* up_w       = (const float*)d_in[8];
    const float* down_w     = (const float*)d_in[9];
    float* out = (float*)d_out;

    __half *p_ln, *p_attn, *p_gate, *p_up;
    float  *p_qkv, *p_h2;
    __half *p_wqkv, *p_wout, *p_wgate, *p_wup, *p_wdown;
    cudaGetSymbolAddress((void**)&p_ln,    g_ln);
    cudaGetSymbolAddress((void**)&p_qkv,   g_qkv);
    cudaGetSymbolAddress((void**)&p_attn,  g_attn);
    cudaGetSymbolAddress((void**)&p_h2,    g_h2);
    cudaGetSymbolAddress((void**)&p_gate,  g_gate);
    cudaGetSymbolAddress((void**)&p_up,    g_up);
    cudaGetSymbolAddress((void**)&p_wqkv,  g_wqkv);
    cudaGetSymbolAddress((void**)&p_wout,  g_wout);
    cudaGetSymbolAddress((void**)&p_wgate, g_wgate);
    cudaGetSymbolAddress((void**)&p_wup,   g_wup);
    cudaGetSymbolAddress((void**)&p_wdown, g_wdown);

    cudaFuncSetAttribute((const void*)gemm_f16_kernel,
                         cudaFuncAttributeMaxDynamicSharedMemorySize, GEMM_SMEM_BYTES);
    cudaFuncSetAttribute((const void*)attn_kernel,
                         cudaFuncAttributeMaxDynamicSharedMemorySize, ATTN_SMEM_BYTES);

    // 0. weight fp16 conversion
    {
        int n4;
        n4 = (QKV3 * DIM) / 4;
        cvtw_kernel<<<(n4 + 255) / 256, 256>>>((const float4*)in_proj_w, (__half2*)p_wqkv, n4);
        n4 = (DIM * DIM) / 4;
        cvtw_kernel<<<(n4 + 255) / 256, 256>>>((const float4*)out_proj_w, (__half2*)p_wout, n4);
        n4 = (FDIM * DIM) / 4;
        cvtw_kernel<<<(n4 + 255) / 256, 256>>>((const float4*)gate_w, (__half2*)p_wgate, n4);
        cvtw_kernel<<<(n4 + 255) / 256, 256>>>((const float4*)up_w, (__half2*)p_wup, n4);
        cvtw_kernel<<<(n4 + 255) / 256, 256>>>((const float4*)down_w, (__half2*)p_wdown, n4);
    }

    // 1. rmsnorm1 (fp16 out)
    rmsnorm_kernel<<<TOTAL, 256>>>(hidden, ln1_w, p_ln);
    // 2. qkv projection (fp32 out for attention)
    gemm_f16_kernel<<<dim3(QKV3 / 128, TOTAL / 128), 256, GEMM_SMEM_BYTES>>>(
        p_ln, p_wqkv, in_proj_b, nullptr, p_qkv, nullptr, TOTAL, QKV3, DIM);
    // 3. attention (fp16 out)
    attn_kernel<<<dim3(TOTAL / 128, HEADS), 256, ATTN_SMEM_BYTES>>>(p_qkv, p_attn);
    // 4. out projection + residual (fp32 out)
    gemm_f16_kernel<<<dim3(DIM / 128, TOTAL / 128), 256, GEMM_SMEM_BYTES>>>(
        p_attn, p_wout, out_proj_b, hidden, p_h2, nullptr, TOTAL, DIM, DIM);
    // 5. rmsnorm2 (fp16 out)
    rmsnorm_kernel<<<TOTAL, 256>>>(p_h2, ln2_w, p_ln);
    // 6/7. gate & up projections (fp16 out)
    gemm_f16_kernel<<<dim3(FDIM / 128, TOTAL / 128), 256, GEMM_SMEM_BYTES>>>(
        p_ln, p_wgate, nullptr, nullptr, nullptr, p_gate, TOTAL, FDIM, DIM);
    gemm_f16_kernel<<<dim3(FDIM / 128, TOTAL / 128), 256, GEMM_SMEM_BYTES>>>(
        p_ln, p_wup, nullptr, nullptr, nullptr, p_up, TOTAL, FDIM, DIM);
    // 8. sigmoid gate (fp16 out)
    int n2 = (TOTAL * FDIM) / 2;
    gate_kernel<<<(n2 + 255) / 256, 256>>>((__half2*)p_gate, (const __half2*)p_up, n2);
    // 9. down projection + residual -> output (fp32)
    gemm_f16_kernel<<<dim3(DIM / 128, TOTAL / 128), 256, GEMM_SMEM_BYTES>>>(
        p_gate, p_wdown, nullptr, p_h2, out, nullptr, TOTAL, DIM, FDIM);
}